// round 6
// baseline (speedup 1.0000x reference)
#include <cuda_runtime.h>
#include <cuda_bf16.h>

#define BB 2
#define NN 1024
#define DD 16
#define HH 8
#define W1STRIDE (3 * DD + 1)   // 49

typedef unsigned long long ull;

__device__ __forceinline__ float tanh_approx(float x) {
    float y;
    asm("tanh.approx.f32 %0, %1;" : "=f"(y) : "f"(x));
    return y;
}
__device__ __forceinline__ ull pack2(float lo, float hi) {
    ull d;
    asm("mov.b64 %0, {%1, %2};" : "=l"(d) : "f"(lo), "f"(hi));
    return d;
}
__device__ __forceinline__ void unpack2(ull v, float& lo, float& hi) {
    asm("mov.b64 {%0, %1}, %2;" : "=f"(lo), "=f"(hi) : "l"(v));
}
__device__ __forceinline__ ull fma2(ull a, ull b, ull c) {
    ull d;
    asm("fma.rn.f32x2 %0, %1, %2, %3;" : "=l"(d) : "l"(a), "l"(b), "l"(c));
    return d;
}
__device__ __forceinline__ ull add2(ull a, ull b) {
    ull d;
    asm("add.rn.f32x2 %0, %1, %2;" : "=l"(d) : "l"(a), "l"(b));
    return d;
}
__device__ __forceinline__ ull tanh2(ull v) {
    float lo, hi;
    unpack2(v, lo, hi);
    return pack2(tanh_approx(lo), tanh_approx(hi));
}

// ---------------------------------------------------------------------------
// Fused kernel. Tile = 32 i x 64 j per block (256 threads); each thread
// computes 8 edges (1 i, 8 consecutive j) as 4 packed f32x2 lanes, so each
// uniform weight LDS.128 feeds 8 FFMA2.
// ---------------------------------------------------------------------------
__global__ __launch_bounds__(256, 2)
void edge_mlp_kernel(const float* __restrict__ x,
                     const float* __restrict__ A,
                     const float* __restrict__ vp,
                     const float* __restrict__ W1, const float* __restrict__ b1,
                     const float* __restrict__ W2, const float* __restrict__ b2,
                     const float* __restrict__ W3, const float* __restrict__ b3,
                     const float* __restrict__ W4, const float* __restrict__ b4,
                     const float* __restrict__ W5, const float* __restrict__ b5,
                     float* __restrict__ out) {
    __shared__ __align__(16) float s_xj[64][DD];      // x rows for j tile
    __shared__ __align__(16) float s_xi[32][DD];      // x rows for i tile
    __shared__ __align__(16) float s_w1[HH * W1STRIDE];
    __shared__ __align__(16) float s_tjt[HH][64];     // t_j transposed [h][j]
    __shared__ __align__(16) float s_ti[32 * HH];     // t_i + t_v + b1, [i][h]
    __shared__ __align__(16) ull   s_wd[3][HH * HH];  // W-l transposed [h][k], dup pairs
    __shared__ __align__(16) ull   s_bd[3][HH];
    __shared__ __align__(16) ull   s_w5d[HH];
    __shared__ __align__(16) ull   s_w1ad[HH];
    __shared__ float s_vp[DD];
    __shared__ float s_b1[HH];
    __shared__ ull   s_b5d;

    const int tid = threadIdx.x;
    const int b  = blockIdx.z;
    const int i0 = blockIdx.y * 32;
    const int j0 = blockIdx.x * 64;

    // --- phase 1: stage x rows + all weights into shared ---
    {
        // 96 rows x 4 float4 = 384 float4 loads
#pragma unroll
        for (int idx = tid; idx < 384; idx += 256) {
            int r  = idx >> 2;
            int c4 = (idx & 3) * 4;
            if (r < 64) {
                float4 v = *reinterpret_cast<const float4*>(
                    x + ((size_t)(b * NN + j0 + r)) * DD + c4);
                s_xj[r][c4] = v.x; s_xj[r][c4 + 1] = v.y;
                s_xj[r][c4 + 2] = v.z; s_xj[r][c4 + 3] = v.w;
            } else {
                int rr = r - 64;
                float4 v = *reinterpret_cast<const float4*>(
                    x + ((size_t)(b * NN + i0 + rr)) * DD + c4);
                s_xi[rr][c4] = v.x; s_xi[rr][c4 + 1] = v.y;
                s_xi[rr][c4 + 2] = v.z; s_xi[rr][c4 + 3] = v.w;
            }
        }
        s_w1[tid] = W1[tid];
        if (tid < HH * W1STRIDE - 256) s_w1[256 + tid] = W1[256 + tid];
        if (tid < 64) {
            int dstT = (tid & 7) * HH + (tid >> 3);   // [k][h] -> [h][k]
            float w2 = W2[tid], w3 = W3[tid], w4 = W4[tid];
            s_wd[0][dstT] = pack2(w2, w2);
            s_wd[1][dstT] = pack2(w3, w3);
            s_wd[2][dstT] = pack2(w4, w4);
        }
        if (tid < DD) s_vp[tid] = vp[b * DD + tid];
        if (tid < 8) {
            float v2 = b2[tid], v3 = b3[tid], v4 = b4[tid];
            s_bd[0][tid] = pack2(v2, v2);
            s_bd[1][tid] = pack2(v3, v3);
            s_bd[2][tid] = pack2(v4, v4);
            float w5 = W5[tid];
            s_w5d[tid] = pack2(w5, w5);
            float wa = W1[tid * W1STRIDE + 3 * DD];
            s_w1ad[tid] = pack2(wa, wa);
            s_b1[tid] = b1[tid];
        }
        if (tid == 0) { float v = b5[0]; s_b5d = pack2(v, v); }
    }
    __syncthreads();

    // --- phase 2: row projections (t_j for 64 rows, t_i for 32 rows) ---
    {
        int n = tid >> 3;      // 0..31
        int h = tid & 7;
        const float* wr = s_w1 + h * W1STRIDE;
        float tj0 = 0.0f, tj1 = 0.0f, ti = 0.0f, tv = s_b1[h];
#pragma unroll
        for (int c = 0; c < DD; c++) {
            tj0 += s_xj[n][c]      * wr[c];
            tj1 += s_xj[n + 32][c] * wr[c];
            ti  += s_xi[n][c]      * wr[DD + c];
            tv  += s_vp[c]         * wr[2 * DD + c];
        }
        s_tjt[h][n]      = tj0;
        s_tjt[h][n + 32] = tj1;
        s_ti[n * HH + h] = ti + tv;
    }
    __syncthreads();

    // --- phase 3: packed edge MLP, 4 lanes (8 edges) ---
    const int ii = tid >> 3;         // 0..31
    const int jl = (tid & 7) * 8;    // 0,8,...,56

    const size_t off = ((size_t)(b * NN + i0 + ii)) * NN + j0 + jl;
    float4 aA = *reinterpret_cast<const float4*>(A + off);
    float4 aB = *reinterpret_cast<const float4*>(A + off + 4);
    ull a2[4] = { pack2(aA.x, aA.y), pack2(aA.z, aA.w),
                  pack2(aB.x, aB.y), pack2(aB.z, aB.w) };

    // layer 1
    ull h2[4][HH];
#pragma unroll
    for (int h = 0; h < HH; h++) {
        float4 tjA = *reinterpret_cast<const float4*>(&s_tjt[h][jl]);
        float4 tjB = *reinterpret_cast<const float4*>(&s_tjt[h][jl + 4]);
        float tival = s_ti[ii * HH + h];
        ull tiv = pack2(tival, tival);
        ull wa  = s_w1ad[h];
        h2[0][h] = tanh2(fma2(a2[0], wa, add2(pack2(tjA.x, tjA.y), tiv)));
        h2[1][h] = tanh2(fma2(a2[1], wa, add2(pack2(tjA.z, tjA.w), tiv)));
        h2[2][h] = tanh2(fma2(a2[2], wa, add2(pack2(tjB.x, tjB.y), tiv)));
        h2[3][h] = tanh2(fma2(a2[3], wa, add2(pack2(tjB.z, tjB.w), tiv)));
    }

    // layers 2..4: h outer, k inner; 32 independent acc chains
#pragma unroll
    for (int l = 0; l < 3; l++) {
        ull acc[4][HH];
#pragma unroll
        for (int k = 0; k < HH; k += 2) {
            ulonglong2 bk = *reinterpret_cast<const ulonglong2*>(&s_bd[l][k]);
#pragma unroll
            for (int p = 0; p < 4; p++) {
                acc[p][k]     = bk.x;
                acc[p][k + 1] = bk.y;
            }
        }
#pragma unroll
        for (int h = 0; h < HH; h++) {
            ull hv0 = h2[0][h], hv1 = h2[1][h];
            ull hv2 = h2[2][h], hv3 = h2[3][h];
#pragma unroll
            for (int kp = 0; kp < HH / 2; kp++) {
                ulonglong2 w = *reinterpret_cast<const ulonglong2*>(&s_wd[l][h * HH + kp * 2]);
                acc[0][kp * 2]     = fma2(hv0, w.x, acc[0][kp * 2]);
                acc[1][kp * 2]     = fma2(hv1, w.x, acc[1][kp * 2]);
                acc[2][kp * 2]     = fma2(hv2, w.x, acc[2][kp * 2]);
                acc[3][kp * 2]     = fma2(hv3, w.x, acc[3][kp * 2]);
                acc[0][kp * 2 + 1] = fma2(hv0, w.y, acc[0][kp * 2 + 1]);
                acc[1][kp * 2 + 1] = fma2(hv1, w.y, acc[1][kp * 2 + 1]);
                acc[2][kp * 2 + 1] = fma2(hv2, w.y, acc[2][kp * 2 + 1]);
                acc[3][kp * 2 + 1] = fma2(hv3, w.y, acc[3][kp * 2 + 1]);
            }
        }
#pragma unroll
        for (int p = 0; p < 4; p++)
#pragma unroll
            for (int k = 0; k < HH; k++)
                h2[p][k] = tanh2(acc[p][k]);
    }

    // output layer
    ull o2[4] = { s_b5d, s_b5d, s_b5d, s_b5d };
#pragma unroll
    for (int h = 0; h < HH; h++) {
        ull w = s_w5d[h];
        o2[0] = fma2(h2[0][h], w, o2[0]);
        o2[1] = fma2(h2[1][h], w, o2[1]);
        o2[2] = fma2(h2[2][h], w, o2[2]);
        o2[3] = fma2(h2[3][h], w, o2[3]);
    }
    float4 oA, oB;
    unpack2(o2[0], oA.x, oA.y);
    unpack2(o2[1], oA.z, oA.w);
    unpack2(o2[2], oB.x, oB.y);
    unpack2(o2[3], oB.z, oB.w);
    *reinterpret_cast<float4*>(out + off)     = oA;
    *reinterpret_cast<float4*>(out + off + 4) = oB;
}

// ---------------------------------------------------------------------------
extern "C" void kernel_launch(void* const* d_in, const int* in_sizes, int n_in,
                              void* d_out, int out_size) {
    const float* x  = (const float*)d_in[0];
    const float* A  = (const float*)d_in[1];
    const float* vp = (const float*)d_in[2];
    const float* W1 = (const float*)d_in[3];
    const float* b1 = (const float*)d_in[4];
    const float* W2 = (const float*)d_in[5];
    const float* b2 = (const float*)d_in[6];
    const float* W3 = (const float*)d_in[7];
    const float* b3 = (const float*)d_in[8];
    const float* W4 = (const float*)d_in[9];
    const float* b4 = (const float*)d_in[10];
    const float* W5 = (const float*)d_in[11];
    const float* b5 = (const float*)d_in[12];
    float* out = (float*)d_out;

    dim3 grid(NN / 64, NN / 32, BB);   // 16 x 32 x 2 = 1024 blocks
    edge_mlp_kernel<<<grid, 256>>>(x, A, vp, W1, b1, W2, b2, W3, b3,
                                   W4, b4, W5, b5, out);
}